// round 1
// baseline (speedup 1.0000x reference)
#include <cuda_runtime.h>
#include <math.h>

#define BB 8
#define NN 2048
#define DD 128
#define CC 256
#define MM (BB*NN)   // 16384

// Scratch (static device allocations are allowed)
__device__ float g_H[MM*CC];      // h for both heads, [row][head*128+col]
__device__ float g_feat[MM*CC];   // layer-2 input (concat of layer-1 attention outputs)
__device__ float g_el[2*MM];
__device__ float g_er[2*MM];
__device__ float g_P[2*MM];
__device__ float g_Q[2*MM];
__device__ float g_R[2*MM];
__device__ float g_S[2*MM];

// ---------------------------------------------------------------------------
// K1: C[row][head*128+col] = X[row][:] @ W_head[:, col] + b_head[col]
// X: [M,256], W: [256,128]. Block tile 128x128, 256 threads, 8x8 microtile.
// grid = (M/128, 2)
// ---------------------------------------------------------------------------
__global__ __launch_bounds__(256) void gemm_bias_kernel(
    const float* __restrict__ X,
    const float* __restrict__ W0, const float* __restrict__ W1,
    const float* __restrict__ b0, const float* __restrict__ b1,
    float* __restrict__ C)
{
    const int head = blockIdx.y;
    const float* __restrict__ W    = head ? W1 : W0;
    const float* __restrict__ bias = head ? b1 : b0;
    const int m0 = blockIdx.x * 128;

    __shared__ float As[16][128];   // [k][m]
    __shared__ float Bs[16][128];   // [k][n]

    const int t  = threadIdx.x;
    const int tx = t & 15;
    const int ty = t >> 4;

    float acc[8][8];
#pragma unroll
    for (int r = 0; r < 8; r++)
#pragma unroll
        for (int c = 0; c < 8; c++) acc[r][c] = 0.f;

    for (int k0 = 0; k0 < 256; k0 += 16) {
#pragma unroll
        for (int i = 0; i < 2; i++) {
            int s   = t * 2 + i;          // 0..511
            int row = s >> 2;             // 0..127
            int kk  = (s & 3) * 4;        // 0,4,8,12
            float4 v = *(const float4*)(X + (size_t)(m0 + row) * 256 + k0 + kk);
            As[kk + 0][row] = v.x;
            As[kk + 1][row] = v.y;
            As[kk + 2][row] = v.z;
            As[kk + 3][row] = v.w;
        }
#pragma unroll
        for (int i = 0; i < 2; i++) {
            int s  = t * 2 + i;           // 0..511
            int kk = s >> 5;              // 0..15
            int cc = (s & 31) * 4;        // 0..124
            *(float4*)&Bs[kk][cc] = *(const float4*)(W + (size_t)(k0 + kk) * 128 + cc);
        }
        __syncthreads();

#pragma unroll
        for (int k = 0; k < 16; k++) {
            const float4* ap = (const float4*)&As[k][ty * 8];
            const float4* bp = (const float4*)&Bs[k][tx * 8];
            float4 a0 = ap[0], a1 = ap[1];
            float4 bq0 = bp[0], bq1 = bp[1];
            float a[8] = {a0.x, a0.y, a0.z, a0.w, a1.x, a1.y, a1.z, a1.w};
            float bb[8] = {bq0.x, bq0.y, bq0.z, bq0.w, bq1.x, bq1.y, bq1.z, bq1.w};
#pragma unroll
            for (int r = 0; r < 8; r++)
#pragma unroll
                for (int c = 0; c < 8; c++) acc[r][c] += a[r] * bb[c];
        }
        __syncthreads();
    }

#pragma unroll
    for (int r = 0; r < 8; r++) {
        int row = m0 + ty * 8 + r;
        float* cp = C + (size_t)row * 256 + head * 128 + tx * 8;
#pragma unroll
        for (int c = 0; c < 8; c += 4) {
            float4 v;
            v.x = acc[r][c + 0] + bias[tx * 8 + c + 0];
            v.y = acc[r][c + 1] + bias[tx * 8 + c + 1];
            v.z = acc[r][c + 2] + bias[tx * 8 + c + 2];
            v.w = acc[r][c + 3] + bias[tx * 8 + c + 3];
            *(float4*)(cp + c) = v;
        }
    }
}

// ---------------------------------------------------------------------------
// K2: el[row] = h_row . a[:128], er[row] = h_row . a[128:]  (one warp per row,head)
// grid*block = 2*M warps
// ---------------------------------------------------------------------------
__global__ __launch_bounds__(256) void elr_kernel(
    const float* __restrict__ a0, const float* __restrict__ a1,
    const float* __restrict__ H)
{
    int gw   = (blockIdx.x * blockDim.x + threadIdx.x) >> 5;  // 0..2M-1
    int lane = threadIdx.x & 31;
    if (gw >= 2 * MM) return;
    int head = gw >> 14;                // M = 2^14
    int row  = gw & (MM - 1);
    const float* __restrict__ a = head ? a1 : a0;
    const float* __restrict__ h = H + (size_t)row * 256 + head * 128;

    float el = 0.f, er = 0.f;
#pragma unroll
    for (int i = 0; i < 4; i++) {
        int idx = lane + i * 32;
        float hv = h[idx];
        el += hv * a[idx];
        er += hv * a[128 + idx];
    }
#pragma unroll
    for (int o = 16; o > 0; o >>= 1) {
        el += __shfl_xor_sync(0xFFFFFFFFu, el, o);
        er += __shfl_xor_sync(0xFFFFFFFFu, er, o);
    }
    if (lane == 0) { g_el[gw] = el; g_er[gw] = er; }
}

// ---------------------------------------------------------------------------
// K3: per (head,b): er_max, then P=exp(el-m), Q=exp(.2el-m), R=exp(er), S=exp(.2er)
// with m_i = leakyrelu(el_i + er_max).  grid = 16 blocks of 256.
// ---------------------------------------------------------------------------
__global__ __launch_bounds__(256) void maxpqrs_kernel()
{
    int head = blockIdx.x >> 3;
    int b    = blockIdx.x & 7;
    int base = head * MM + b * NN;

    __shared__ float red[256];
    float m = -1e30f;
    for (int i = threadIdx.x; i < NN; i += 256) m = fmaxf(m, g_er[base + i]);
    red[threadIdx.x] = m;
    __syncthreads();
    for (int s = 128; s > 0; s >>= 1) {
        if (threadIdx.x < s) red[threadIdx.x] = fmaxf(red[threadIdx.x], red[threadIdx.x + s]);
        __syncthreads();
    }
    float ermax = red[0];

    for (int i = threadIdx.x; i < NN; i += 256) {
        float el = g_el[base + i];
        float er = g_er[base + i];
        float tv = el + ermax;
        float mi = tv > 0.f ? tv : 0.2f * tv;
        g_P[base + i] = expf(el - mi);
        g_Q[base + i] = expf(0.2f * el - mi);
        g_R[base + i] = expf(er);
        g_S[base + i] = expf(0.2f * er);
    }
}

// ---------------------------------------------------------------------------
// K4: attention.  out[i] = elu( (sum_{j!=i} w_ij h_j)/Z_i + h_i )
// w_ij = (el_i+er_j > 0) ? P_i*R_j : Q_i*S_j     (= exp(lrelu(el_i+er_j)-m_i))
// Block: 128 i-rows x 128 cols, 256 threads, j staged in 32-row smem tiles.
// grid = (N/128, B, 2)
// ---------------------------------------------------------------------------
__global__ __launch_bounds__(256) void attn_kernel(
    const float* __restrict__ H, float* __restrict__ Out)
{
    const int head = blockIdx.z;
    const int b    = blockIdx.y;
    const int i0   = blockIdx.x * 128;
    const int rowbase = head * MM + b * NN;
    const float* __restrict__ Hb = H + (size_t)b * NN * 256 + head * 128;

    __shared__ float Hs[32][128];
    __shared__ float ers[32], Rs[32], Ss[32];

    const int t  = threadIdx.x;
    const int tx = t & 15;
    const int ty = t >> 4;

    float acc[8][8];
    float Z[8];
    float el_r[8], P_r[8], Q_r[8];
#pragma unroll
    for (int r = 0; r < 8; r++) {
        Z[r] = 0.f;
#pragma unroll
        for (int c = 0; c < 8; c++) acc[r][c] = 0.f;
        int i = i0 + ty * 8 + r;
        el_r[r] = g_el[rowbase + i];
        P_r[r]  = g_P[rowbase + i];
        Q_r[r]  = g_Q[rowbase + i];
    }

    for (int j0 = 0; j0 < NN; j0 += 32) {
#pragma unroll
        for (int i2 = 0; i2 < 4; i2++) {
            int s  = t + i2 * 256;        // 0..1023 float4 slots
            int jr = s >> 5;              // 0..31
            int cc = (s & 31) * 4;        // 0..124
            *(float4*)&Hs[jr][cc] = *(const float4*)(Hb + (size_t)(j0 + jr) * 256 + cc);
        }
        if (t < 32) {
            int j = j0 + t;
            ers[t] = g_er[rowbase + j];
            Rs[t]  = g_R[rowbase + j];
            Ss[t]  = g_S[rowbase + j];
        }
        __syncthreads();

#pragma unroll 8
        for (int jj = 0; jj < 32; jj++) {
            float er = ers[jj], Rv = Rs[jj], Sv = Ss[jj];
            float4 h0 = *(const float4*)&Hs[jj][tx * 8];
            float4 h1 = *(const float4*)&Hs[jj][tx * 8 + 4];
#pragma unroll
            for (int r = 0; r < 8; r++) {
                float tv = el_r[r] + er;
                float w  = (tv > 0.f) ? P_r[r] * Rv : Q_r[r] * Sv;
                Z[r] += w;
                acc[r][0] += w * h0.x; acc[r][1] += w * h0.y;
                acc[r][2] += w * h0.z; acc[r][3] += w * h0.w;
                acc[r][4] += w * h1.x; acc[r][5] += w * h1.y;
                acc[r][6] += w * h1.z; acc[r][7] += w * h1.w;
            }
        }
        __syncthreads();
    }

    // diagonal correction, identity add, elu, store
#pragma unroll
    for (int r = 0; r < 8; r++) {
        int i = i0 + ty * 8 + r;
        float er_i = g_er[rowbase + i];
        float R_i  = g_R[rowbase + i];
        float S_i  = g_S[rowbase + i];
        float tv   = el_r[r] + er_i;
        float wii  = (tv > 0.f) ? P_r[r] * R_i : Q_r[r] * S_i;
        float inv  = 1.0f / (Z[r] - wii);

        const float* hi = Hb + (size_t)i * 256 + tx * 8;
        float out8[8];
#pragma unroll
        for (int c = 0; c < 8; c++) {
            float hv = hi[c];
            float v  = (acc[r][c] - wii * hv) * inv + hv;
            out8[c]  = v > 0.f ? v : expm1f(v);
        }
        float* op = Out + (size_t)(b * NN + i) * 256 + head * 128 + tx * 8;
        *(float4*)(op + 0) = make_float4(out8[0], out8[1], out8[2], out8[3]);
        *(float4*)(op + 4) = make_float4(out8[4], out8[5], out8[6], out8[7]);
    }
}

// ---------------------------------------------------------------------------
extern "C" void kernel_launch(void* const* d_in, const int* in_sizes, int n_in,
                              void* d_out, int out_size)
{
    const float* x   = (const float*)d_in[0];
    // d_in[1] = edges (unused by reference)
    const float* W00 = (const float*)d_in[2];
    const float* b00 = (const float*)d_in[3];
    const float* a00 = (const float*)d_in[4];
    const float* W01 = (const float*)d_in[5];
    const float* b01 = (const float*)d_in[6];
    const float* a01 = (const float*)d_in[7];
    const float* W10 = (const float*)d_in[8];
    const float* b10 = (const float*)d_in[9];
    const float* a10 = (const float*)d_in[10];
    const float* W11 = (const float*)d_in[11];
    const float* b11 = (const float*)d_in[12];
    const float* a11 = (const float*)d_in[13];
    float* out = (float*)d_out;

    float *H, *feat;
    cudaGetSymbolAddress((void**)&H,    g_H);
    cudaGetSymbolAddress((void**)&feat, g_feat);

    dim3 gemm_grid(MM / 128, 2);
    dim3 attn_grid(NN / 128, BB, 2);

    // ---- Layer 1 ----
    gemm_bias_kernel<<<gemm_grid, 256>>>(x, W00, W01, b00, b01, H);
    elr_kernel<<<(2 * MM) / 8, 256>>>(a00, a01, H);
    maxpqrs_kernel<<<16, 256>>>();
    attn_kernel<<<attn_grid, 256>>>(H, feat);

    // ---- Layer 2 ----
    gemm_bias_kernel<<<gemm_grid, 256>>>(feat, W10, W11, b10, b11, H);
    elr_kernel<<<(2 * MM) / 8, 256>>>(a10, a11, H);
    maxpqrs_kernel<<<16, 256>>>();
    attn_kernel<<<attn_grid, 256>>>(H, out);
}

// round 3
// speedup vs baseline: 3.3039x; 3.3039x over previous
#include <cuda_runtime.h>
#include <math.h>
#include <stdint.h>

#define BB 8
#define NN 2048
#define CC 256
#define MM (BB*NN)   // 16384

// ---------------- scratch ----------------
__device__ float g_H[MM*CC];            // h (row-major), both heads concat
__device__ float g_feat[MM*CC];         // layer-2 input
__device__ float g_el[2*MM];
__device__ float g_er[2*MM];
__device__ float g_P[2*MM];
__device__ float g_Q[2*MM];
__device__ float g_R[2*MM];
__device__ float g_S[2*MM];

__device__ __forceinline__ uint32_t cvt_tf32(float f) {
    uint32_t r; asm("cvt.rna.tf32.f32 %0, %1;" : "=r"(r) : "f"(f)); return r;
}

// ---------------------------------------------------------------------------
// K1: h = X @ W + b (both heads). grid = (M/128, 2), block = 256
// ---------------------------------------------------------------------------
__global__ __launch_bounds__(256) void gemm_bias_kernel(
    const float* __restrict__ X,
    const float* __restrict__ W0, const float* __restrict__ W1,
    const float* __restrict__ b0, const float* __restrict__ b1,
    float* __restrict__ C)
{
    const int head = blockIdx.y;
    const float* __restrict__ W    = head ? W1 : W0;
    const float* __restrict__ bias = head ? b1 : b0;
    const int m0 = blockIdx.x * 128;

    __shared__ float As[16][128];
    __shared__ float Bs[16][128];

    const int t  = threadIdx.x;
    const int tx = t & 15;
    const int ty = t >> 4;

    float acc[8][8];
#pragma unroll
    for (int r = 0; r < 8; r++)
#pragma unroll
        for (int c = 0; c < 8; c++) acc[r][c] = 0.f;

    for (int k0 = 0; k0 < 256; k0 += 16) {
#pragma unroll
        for (int i = 0; i < 2; i++) {
            int s   = t * 2 + i;
            int row = s >> 2;
            int kk  = (s & 3) * 4;
            float4 v = *(const float4*)(X + (size_t)(m0 + row) * 256 + k0 + kk);
            As[kk + 0][row] = v.x;
            As[kk + 1][row] = v.y;
            As[kk + 2][row] = v.z;
            As[kk + 3][row] = v.w;
        }
#pragma unroll
        for (int i = 0; i < 2; i++) {
            int s  = t * 2 + i;
            int kk = s >> 5;
            int cc = (s & 31) * 4;
            *(float4*)&Bs[kk][cc] = *(const float4*)(W + (size_t)(k0 + kk) * 128 + cc);
        }
        __syncthreads();

#pragma unroll
        for (int k = 0; k < 16; k++) {
            const float4* ap = (const float4*)&As[k][ty * 8];
            const float4* bp = (const float4*)&Bs[k][tx * 8];
            float4 a0 = ap[0], a1 = ap[1];
            float4 bq0 = bp[0], bq1 = bp[1];
            float a[8] = {a0.x, a0.y, a0.z, a0.w, a1.x, a1.y, a1.z, a1.w};
            float bb[8] = {bq0.x, bq0.y, bq0.z, bq0.w, bq1.x, bq1.y, bq1.z, bq1.w};
#pragma unroll
            for (int r = 0; r < 8; r++)
#pragma unroll
                for (int c = 0; c < 8; c++) acc[r][c] += a[r] * bb[c];
        }
        __syncthreads();
    }

#pragma unroll
    for (int r = 0; r < 8; r++) {
        int row = m0 + ty * 8 + r;
        float* cp = C + (size_t)row * 256 + head * 128 + tx * 8;
#pragma unroll
        for (int c = 0; c < 8; c += 4) {
            float4 v;
            v.x = acc[r][c + 0] + bias[tx * 8 + c + 0];
            v.y = acc[r][c + 1] + bias[tx * 8 + c + 1];
            v.z = acc[r][c + 2] + bias[tx * 8 + c + 2];
            v.w = acc[r][c + 3] + bias[tx * 8 + c + 3];
            *(float4*)(cp + c) = v;
        }
    }
}

// ---------------------------------------------------------------------------
// K2: el/er per (head,row)
// ---------------------------------------------------------------------------
__global__ __launch_bounds__(256) void elr_kernel(
    const float* __restrict__ a0, const float* __restrict__ a1,
    const float* __restrict__ H)
{
    int gw   = (blockIdx.x * blockDim.x + threadIdx.x) >> 5;
    int lane = threadIdx.x & 31;
    if (gw >= 2 * MM) return;
    int head = gw >> 14;
    int row  = gw & (MM - 1);
    const float* __restrict__ a = head ? a1 : a0;
    const float* __restrict__ h = H + (size_t)row * 256 + head * 128;

    float el = 0.f, er = 0.f;
#pragma unroll
    for (int i = 0; i < 4; i++) {
        int idx = lane + i * 32;
        float hv = h[idx];
        el += hv * a[idx];
        er += hv * a[128 + idx];
    }
#pragma unroll
    for (int o = 16; o > 0; o >>= 1) {
        el += __shfl_xor_sync(0xFFFFFFFFu, el, o);
        er += __shfl_xor_sync(0xFFFFFFFFu, er, o);
    }
    if (lane == 0) { g_el[gw] = el; g_er[gw] = er; }
}

// ---------------------------------------------------------------------------
// K3: per (head,b): er_max, then P/Q/R/S
// ---------------------------------------------------------------------------
__global__ __launch_bounds__(256) void maxpqrs_kernel()
{
    int head = blockIdx.x >> 3;
    int b    = blockIdx.x & 7;
    int base = head * MM + b * NN;

    __shared__ float red[256];
    float m = -1e30f;
    for (int i = threadIdx.x; i < NN; i += 256) m = fmaxf(m, g_er[base + i]);
    red[threadIdx.x] = m;
    __syncthreads();
    for (int s = 128; s > 0; s >>= 1) {
        if (threadIdx.x < s) red[threadIdx.x] = fmaxf(red[threadIdx.x], red[threadIdx.x + s]);
        __syncthreads();
    }
    float ermax = red[0];

    for (int i = threadIdx.x; i < NN; i += 256) {
        float el = g_el[base + i];
        float er = g_er[base + i];
        float tv = el + ermax;
        float mi = tv > 0.f ? tv : 0.2f * tv;
        g_P[base + i] = expf(el - mi);
        g_Q[base + i] = expf(0.2f * el - mi);
        g_R[base + i] = expf(er);
        g_S[base + i] = expf(0.2f * er);
    }
}

// ---------------------------------------------------------------------------
// K4: attention via mma.sync tf32 m16n8k8.
// CTA = (b, head, 128 i-rows). 8 warps, warp tile M=16 x N=128.
// Loop 64 chunks of 32 j: stage B (rows=j, cols=d) in smem (tf32-rounded),
// materialize A weight fragments in registers, 4 k-steps x 16 mmas.
// Z row-sums accumulated from A fragments (each (i,j) weight exactly once/warp).
// grid = (16, 8, 2), block = 256
// ---------------------------------------------------------------------------
#define BPAD 136

__global__ __launch_bounds__(256) void attn_mma_kernel(
    const float* __restrict__ H, float* __restrict__ Out)
{
    __shared__ float Bs[32][BPAD];
    __shared__ float el_s[128], P_s[128], Q_s[128];
    __shared__ float er_c[32], R_c[32], S_c[32];

    const int t    = threadIdx.x;
    const int warp = t >> 5;
    const int lane = t & 31;
    const int gid  = lane >> 2;   // groupID
    const int tig  = lane & 3;    // threadID_in_group

    const int head = blockIdx.z, b = blockIdx.y, i0 = blockIdx.x * 128;
    const int rowbase = head * MM + b * NN;
    const float* __restrict__ Hb = H + (size_t)b * NN * CC + head * 128;

    if (t < 128) {
        el_s[t] = g_el[rowbase + i0 + t];
        P_s[t]  = g_P[rowbase + i0 + t];
        Q_s[t]  = g_Q[rowbase + i0 + t];
    }
    __syncthreads();

    const int mbase = warp * 16;
    const int iA = mbase + gid;       // local row for a0/a2
    const int iB = iA + 8;            // local row for a1/a3
    const float elA = el_s[iA], PA = P_s[iA], QA = Q_s[iA];
    const float elB = el_s[iB], PB = P_s[iB], QB = Q_s[iB];

    float acc[16][4];
#pragma unroll
    for (int nt = 0; nt < 16; nt++)
#pragma unroll
        for (int c = 0; c < 4; c++) acc[nt][c] = 0.f;
    float z0 = 0.f, z1 = 0.f;

    for (int ch = 0; ch < 64; ch++) {
        const int j0 = ch * 32;
        __syncthreads();   // previous chunk's mma reads done

        // stage B: 32 rows x 128 cols, tf32-rounded
#pragma unroll
        for (int q = 0; q < 4; q++) {
            int idx = q * 256 + t;
            int row = idx >> 5;
            int c4  = (idx & 31) << 2;
            float4 v = *(const float4*)(Hb + (size_t)(j0 + row) * CC + c4);
            Bs[row][c4 + 0] = __uint_as_float(cvt_tf32(v.x));
            Bs[row][c4 + 1] = __uint_as_float(cvt_tf32(v.y));
            Bs[row][c4 + 2] = __uint_as_float(cvt_tf32(v.z));
            Bs[row][c4 + 3] = __uint_as_float(cvt_tf32(v.w));
        }
        if (t < 32) {
            er_c[t] = g_er[rowbase + j0 + t];
            R_c[t]  = g_R[rowbase + j0 + t];
            S_c[t]  = g_S[rowbase + j0 + t];
        }
        __syncthreads();

#pragma unroll
        for (int ks = 0; ks < 4; ks++) {
            const int kb = ks * 8;
            const int jj0 = kb + tig, jj1 = jj0 + 4;
            float er0 = er_c[jj0], R0 = R_c[jj0], S0 = S_c[jj0];
            float er1 = er_c[jj1], R1 = R_c[jj1], S1 = S_c[jj1];

            bool p00 = (elA + er0) > 0.f;
            bool p10 = (elB + er0) > 0.f;
            bool p01 = (elA + er1) > 0.f;
            bool p11 = (elB + er1) > 0.f;
            uint32_t a0 = cvt_tf32((p00 ? PA : QA) * (p00 ? R0 : S0));
            uint32_t a1 = cvt_tf32((p10 ? PB : QB) * (p10 ? R0 : S0));
            uint32_t a2 = cvt_tf32((p01 ? PA : QA) * (p01 ? R1 : S1));
            uint32_t a3 = cvt_tf32((p11 ? PB : QB) * (p11 ? R1 : S1));
            z0 += __uint_as_float(a0) + __uint_as_float(a2);
            z1 += __uint_as_float(a1) + __uint_as_float(a3);

#pragma unroll
            for (int nt = 0; nt < 16; nt++) {
                uint32_t b0 = __float_as_uint(Bs[kb + tig][nt * 8 + gid]);
                uint32_t b1 = __float_as_uint(Bs[kb + tig + 4][nt * 8 + gid]);
                asm volatile(
                    "mma.sync.aligned.m16n8k8.row.col.f32.tf32.tf32.f32 "
                    "{%0,%1,%2,%3}, {%4,%5,%6,%7}, {%8,%9}, {%0,%1,%2,%3};"
                    : "+f"(acc[nt][0]), "+f"(acc[nt][1]),
                      "+f"(acc[nt][2]), "+f"(acc[nt][3])
                    : "r"(a0), "r"(a1), "r"(a2), "r"(a3), "r"(b0), "r"(b1));
            }
        }
    }

    // reduce Z within row-groups (lanes sharing same groupID)
    z0 += __shfl_xor_sync(0xFFFFFFFFu, z0, 1);
    z0 += __shfl_xor_sync(0xFFFFFFFFu, z0, 2);
    z1 += __shfl_xor_sync(0xFFFFFFFFu, z1, 1);
    z1 += __shfl_xor_sync(0xFFFFFFFFu, z1, 2);

    // per-row diagonal term + normalization
    const int giA = i0 + iA, giB = i0 + iB;
    float erA = g_er[rowbase + giA], RA = g_R[rowbase + giA], SA = g_S[rowbase + giA];
    float erB = g_er[rowbase + giB], RB = g_R[rowbase + giB], SB2 = g_S[rowbase + giB];
    float tvA = elA + erA, tvB = elB + erB;
    float wiiA = (tvA > 0.f) ? PA * RA : QA * SA;
    float wiiB = (tvB > 0.f) ? PB * RB : QB * SB2;
    float invA = 1.f / (z0 - wiiA);
    float invB = 1.f / (z1 - wiiB);

    const float* hA = Hb + (size_t)giA * CC;
    const float* hB = Hb + (size_t)giB * CC;
    float* oA = Out + (size_t)(b * NN + giA) * CC + head * 128;
    float* oB = Out + (size_t)(b * NN + giB) * CC + head * 128;

#pragma unroll
    for (int nt = 0; nt < 16; nt++) {
        int col = nt * 8 + tig * 2;
        float2 ha = *(const float2*)(hA + col);
        float2 hb2 = *(const float2*)(hB + col);
        float v0 = (acc[nt][0] - wiiA * ha.x) * invA + ha.x;
        float v1 = (acc[nt][1] - wiiA * ha.y) * invA + ha.y;
        float v2 = (acc[nt][2] - wiiB * hb2.x) * invB + hb2.x;
        float v3 = (acc[nt][3] - wiiB * hb2.y) * invB + hb2.y;
        float2 ra, rb;
        ra.x = v0 > 0.f ? v0 : expm1f(v0);
        ra.y = v1 > 0.f ? v1 : expm1f(v1);
        rb.x = v2 > 0.f ? v2 : expm1f(v2);
        rb.y = v3 > 0.f ? v3 : expm1f(v3);
        *(float2*)(oA + col) = ra;
        *(float2*)(oB + col) = rb;
    }
}

// ---------------------------------------------------------------------------
extern "C" void kernel_launch(void* const* d_in, const int* in_sizes, int n_in,
                              void* d_out, int out_size)
{
    const float* x   = (const float*)d_in[0];
    const float* W00 = (const float*)d_in[2];
    const float* b00 = (const float*)d_in[3];
    const float* a00 = (const float*)d_in[4];
    const float* W01 = (const float*)d_in[5];
    const float* b01 = (const float*)d_in[6];
    const float* a01 = (const float*)d_in[7];
    const float* W10 = (const float*)d_in[8];
    const float* b10 = (const float*)d_in[9];
    const float* a10 = (const float*)d_in[10];
    const float* W11 = (const float*)d_in[11];
    const float* b11 = (const float*)d_in[12];
    const float* a11 = (const float*)d_in[13];
    float* out = (float*)d_out;

    float *H, *feat;
    cudaGetSymbolAddress((void**)&H,    g_H);
    cudaGetSymbolAddress((void**)&feat, g_feat);

    dim3 gemm_grid(MM / 128, 2);
    dim3 attn_grid(NN / 128, BB, 2);

    // ---- Layer 1 ----
    gemm_bias_kernel<<<gemm_grid, 256>>>(x, W00, W01, b00, b01, H);
    elr_kernel<<<(2 * MM) / 8, 256>>>(a00, a01, H);
    maxpqrs_kernel<<<16, 256>>>();
    attn_mma_kernel<<<attn_grid, 256>>>(H, feat);

    // ---- Layer 2 ----
    gemm_bias_kernel<<<gemm_grid, 256>>>(feat, W10, W11, b10, b11, H);
    elr_kernel<<<(2 * MM) / 8, 256>>>(a10, a11, H);
    maxpqrs_kernel<<<16, 256>>>();
    attn_mma_kernel<<<attn_grid, 256>>>(H, out);
}

// round 6
// speedup vs baseline: 3.5795x; 1.0834x over previous
#include <cuda_runtime.h>
#include <math.h>
#include <stdint.h>

#define BB 8
#define NN 2048
#define CC 256
#define MM (BB*NN)   // 16384

// ---------------- scratch ----------------
__device__ float g_H[MM*CC];            // h (row-major, exact), both heads concat
__device__ float g_Htf[MM*CC];          // h rna-rounded to tf32 (attention B operand)
__device__ float g_feat[MM*CC];         // layer-2 input
__device__ float g_el[2*MM];
__device__ float g_er[2*MM];
__device__ float g_P[2*MM];
__device__ float g_Q[2*MM];
__device__ float g_R[2*MM];
__device__ float g_S[2*MM];

// ---------------- helpers ----------------
__device__ __forceinline__ uint32_t smem_u32(const void* p) {
    uint32_t a;
    asm("{ .reg .u64 t; cvta.to.shared.u64 t, %1; cvt.u32.u64 %0, t; }" : "=r"(a) : "l"(p));
    return a;
}
__device__ __forceinline__ uint32_t cvt_tf32(float f) {
    uint32_t r; asm("cvt.rna.tf32.f32 %0, %1;" : "=r"(r) : "f"(f)); return r;
}
__device__ __forceinline__ void cpa16(uint32_t d, const void* s) {
    asm volatile("cp.async.ca.shared.global [%0], [%1], 16;" :: "r"(d), "l"(s));
}
__device__ __forceinline__ void cpa4(uint32_t d, const void* s) {
    asm volatile("cp.async.ca.shared.global [%0], [%1], 4;" :: "r"(d), "l"(s));
}
#define CP_COMMIT() asm volatile("cp.async.commit_group;" ::: "memory")
#define CP_WAIT0()  asm volatile("cp.async.wait_group 0;" ::: "memory")

__device__ __forceinline__ void mma8(float* c, uint32_t a0, uint32_t a1,
                                     uint32_t a2, uint32_t a3,
                                     uint32_t b0, uint32_t b1) {
    asm volatile("mma.sync.aligned.m16n8k8.row.col.f32.tf32.tf32.f32 "
        "{%0,%1,%2,%3}, {%4,%5,%6,%7}, {%8,%9}, {%0,%1,%2,%3};"
        : "+f"(c[0]), "+f"(c[1]), "+f"(c[2]), "+f"(c[3])
        : "r"(a0), "r"(a1), "r"(a2), "r"(a3), "r"(b0), "r"(b1));
}

// ---------------------------------------------------------------------------
// K1: h = X @ W + b via 3-term tf32 split (near-fp32 accuracy).
// grid = (M/128, 2), block = 256. CTA tile 128x128, K chunks of 32.
// 8 warps = 4 Mg x 2 Ng (warp M=32, N=64).
// Writes exact h to C and rna-tf32 h to g_Htf.
// ---------------------------------------------------------------------------
__global__ __launch_bounds__(256) void gemm_mma_kernel(
    const float* __restrict__ X,
    const float* __restrict__ W0, const float* __restrict__ W1,
    const float* __restrict__ b0_, const float* __restrict__ b1_,
    float* __restrict__ C)
{
    __shared__ float Xs[128][36];
    __shared__ float Ws[32][136];

    const int head = blockIdx.y;
    const float* __restrict__ W    = head ? W1 : W0;
    const float* __restrict__ bias = head ? b1_ : b0_;
    const int m0 = blockIdx.x * 128;

    const int t = threadIdx.x, warp = t >> 5, lane = t & 31;
    const int gid = lane >> 2, tig = lane & 3;
    const int Mg = warp >> 1, Ng = warp & 1;
    const int nb = Ng * 64;

    float acc[2][8][4];
#pragma unroll
    for (int f = 0; f < 2; f++)
#pragma unroll
        for (int nt = 0; nt < 8; nt++)
#pragma unroll
            for (int c = 0; c < 4; c++) acc[f][nt][c] = 0.f;

    for (int k0 = 0; k0 < 256; k0 += 32) {
        __syncthreads();
#pragma unroll
        for (int q = 0; q < 4; q++) {
            int idx = q * 256 + t;
            int row = idx >> 3;
            int c4  = (idx & 7) * 4;
            *(float4*)&Xs[row][c4] =
                *(const float4*)(X + (size_t)(m0 + row) * CC + k0 + c4);
        }
#pragma unroll
        for (int q = 0; q < 4; q++) {
            int idx = q * 256 + t;
            int kk  = idx >> 5;
            int n4  = (idx & 31) * 4;
            *(float4*)&Ws[kk][n4] = *(const float4*)(W + (size_t)(k0 + kk) * 128 + n4);
        }
        __syncthreads();

#pragma unroll
        for (int ks = 0; ks < 4; ks++) {
            const int kb = ks * 8;
            uint32_t Ah[2][4], Al[2][4];
#pragma unroll
            for (int f = 0; f < 2; f++) {
                int r0 = Mg * 32 + f * 16 + gid;
                float v[4];
                v[0] = Xs[r0][kb + tig];
                v[1] = Xs[r0 + 8][kb + tig];
                v[2] = Xs[r0][kb + tig + 4];
                v[3] = Xs[r0 + 8][kb + tig + 4];
#pragma unroll
                for (int q = 0; q < 4; q++) {
                    Ah[f][q] = cvt_tf32(v[q]);
                    Al[f][q] = cvt_tf32(v[q] - __uint_as_float(Ah[f][q]));
                }
            }
#pragma unroll
            for (int nt = 0; nt < 8; nt++) {
                int n = nb + nt * 8 + gid;
                float w0 = Ws[kb + tig][n];
                float w1 = Ws[kb + tig + 4][n];
                uint32_t bh0 = cvt_tf32(w0);
                uint32_t bl0 = cvt_tf32(w0 - __uint_as_float(bh0));
                uint32_t bh1 = cvt_tf32(w1);
                uint32_t bl1 = cvt_tf32(w1 - __uint_as_float(bh1));
#pragma unroll
                for (int f = 0; f < 2; f++) {
                    mma8(acc[f][nt], Ah[f][0], Ah[f][1], Ah[f][2], Ah[f][3], bl0, bl1);
                    mma8(acc[f][nt], Al[f][0], Al[f][1], Al[f][2], Al[f][3], bh0, bh1);
                    mma8(acc[f][nt], Ah[f][0], Ah[f][1], Ah[f][2], Ah[f][3], bh0, bh1);
                }
            }
        }
    }

#pragma unroll
    for (int f = 0; f < 2; f++) {
        int r0 = m0 + Mg * 32 + f * 16 + gid;
#pragma unroll
        for (int nt = 0; nt < 8; nt++) {
            int n = nb + nt * 8 + tig * 2;
            float2 bv = *(const float2*)(bias + n);
            float2 o0, o1, t0, t1;
            o0.x = acc[f][nt][0] + bv.x;
            o0.y = acc[f][nt][1] + bv.y;
            o1.x = acc[f][nt][2] + bv.x;
            o1.y = acc[f][nt][3] + bv.y;
            t0.x = __uint_as_float(cvt_tf32(o0.x));
            t0.y = __uint_as_float(cvt_tf32(o0.y));
            t1.x = __uint_as_float(cvt_tf32(o1.x));
            t1.y = __uint_as_float(cvt_tf32(o1.y));
            size_t off0 = (size_t)r0 * 256 + head * 128 + n;
            size_t off1 = (size_t)(r0 + 8) * 256 + head * 128 + n;
            *(float2*)(C + off0)     = o0;
            *(float2*)(C + off1)     = o1;
            *(float2*)(g_Htf + off0) = t0;
            *(float2*)(g_Htf + off1) = t1;
        }
    }
}

// ---------------------------------------------------------------------------
// K2: el/er per (head,row)
// ---------------------------------------------------------------------------
__global__ __launch_bounds__(256) void elr_kernel(
    const float* __restrict__ a0, const float* __restrict__ a1,
    const float* __restrict__ H)
{
    int gw   = (blockIdx.x * blockDim.x + threadIdx.x) >> 5;
    int lane = threadIdx.x & 31;
    if (gw >= 2 * MM) return;
    int head = gw >> 14;
    int row  = gw & (MM - 1);
    const float* __restrict__ a = head ? a1 : a0;
    const float* __restrict__ h = H + (size_t)row * 256 + head * 128;

    float el = 0.f, er = 0.f;
#pragma unroll
    for (int i = 0; i < 4; i++) {
        int idx = lane + i * 32;
        float hv = h[idx];
        el += hv * a[idx];
        er += hv * a[128 + idx];
    }
#pragma unroll
    for (int o = 16; o > 0; o >>= 1) {
        el += __shfl_xor_sync(0xFFFFFFFFu, el, o);
        er += __shfl_xor_sync(0xFFFFFFFFu, er, o);
    }
    if (lane == 0) { g_el[gw] = el; g_er[gw] = er; }
}

// ---------------------------------------------------------------------------
// K3: per (head,b): er_max, then P/Q/R/S
// ---------------------------------------------------------------------------
__global__ __launch_bounds__(256) void maxpqrs_kernel()
{
    int head = blockIdx.x >> 3;
    int b    = blockIdx.x & 7;
    int base = head * MM + b * NN;

    __shared__ float red[256];
    float m = -1e30f;
    for (int i = threadIdx.x; i < NN; i += 256) m = fmaxf(m, g_er[base + i]);
    red[threadIdx.x] = m;
    __syncthreads();
    for (int s = 128; s > 0; s >>= 1) {
        if (threadIdx.x < s) red[threadIdx.x] = fmaxf(red[threadIdx.x], red[threadIdx.x + s]);
        __syncthreads();
    }
    float ermax = red[0];

    for (int i = threadIdx.x; i < NN; i += 256) {
        float el = g_el[base + i];
        float er = g_er[base + i];
        float tv = el + ermax;
        float mi = tv > 0.f ? tv : 0.2f * tv;
        g_P[base + i] = expf(el - mi);
        g_Q[base + i] = expf(0.2f * el - mi);
        g_R[base + i] = expf(er);
        g_S[base + i] = expf(0.2f * er);
    }
}

// ---------------------------------------------------------------------------
// K4: attention via tf32 mma. CTA = (b, head, 128 i-rows).
// 8 warps = 4 Mg x 2 Ng; warp tile M=32 x N=64. 32-j chunks, cp.async
// double-buffered. A weights rna-rounded; Z accumulated from ROUNDED values
// (numerator/Z consistency). B read pre-rounded from g_Htf.
// grid = (16, 8, 2), block = 256
// ---------------------------------------------------------------------------
#define BPAD 136

__global__ __launch_bounds__(256, 2) void attn_mma_kernel(
    const float* __restrict__ H, float* __restrict__ Out)
{
    __shared__ float Bs[2][32][BPAD];
    __shared__ float er_s[2][32], R_s[2][32], S_s[2][32];
    __shared__ float el_s[128], P_s[128], Q_s[128];

    const int t = threadIdx.x, warp = t >> 5, lane = t & 31;
    const int gid = lane >> 2, tig = lane & 3;
    const int Mg = warp >> 1, Ng = warp & 1;
    const int nb = Ng * 64;

    const int head = blockIdx.z, b = blockIdx.y, i0 = blockIdx.x * 128;
    const int rowbase = head * MM + b * NN;
    const float* __restrict__ Hb  = H + (size_t)b * NN * CC + head * 128;
    const float* __restrict__ Hbt = g_Htf + (size_t)b * NN * CC + head * 128;

    if (t < 128) {
        el_s[t] = g_el[rowbase + i0 + t];
        P_s[t]  = g_P[rowbase + i0 + t];
        Q_s[t]  = g_Q[rowbase + i0 + t];
    }

    // ---- prologue: stage chunk 0 into buffer 0 ----
    {
#pragma unroll
        for (int q = 0; q < 4; q++) {
            int idx = q * 256 + t;
            int row = idx >> 5;
            int c4  = (idx & 31) * 4;
            cpa16(smem_u32(&Bs[0][row][c4]), Hbt + (size_t)row * CC + c4);
        }
        if (t < 96) {
            int arr = t >> 5, j = t & 31;
            const float* src = (arr == 0 ? g_er : arr == 1 ? g_R : g_S) + rowbase + j;
            float* dst = (arr == 0 ? er_s[0] : arr == 1 ? R_s[0] : S_s[0]) + j;
            cpa4(smem_u32(dst), src);
        }
        CP_COMMIT();
    }
    __syncthreads();

    // per-thread row constants (4 rows: 2 frags x {low, high})
    float elr_[2][2], Pr[2][2], Qr[2][2];
#pragma unroll
    for (int f = 0; f < 2; f++)
#pragma unroll
        for (int hh = 0; hh < 2; hh++) {
            int r = Mg * 32 + f * 16 + gid + hh * 8;
            elr_[f][hh] = el_s[r];
            Pr[f][hh]   = P_s[r];
            Qr[f][hh]   = Q_s[r];
        }

    float acc[2][8][4];
    float z[2][2];
#pragma unroll
    for (int f = 0; f < 2; f++) {
        z[f][0] = z[f][1] = 0.f;
#pragma unroll
        for (int nt = 0; nt < 8; nt++)
#pragma unroll
            for (int c = 0; c < 4; c++) acc[f][nt][c] = 0.f;
    }

    for (int ch = 0; ch < 64; ch++) {
        const int cur = ch & 1;
        CP_WAIT0();
        __syncthreads();

        if (ch < 63) {
            const int nx = cur ^ 1;
            const int j0 = (ch + 1) * 32;
#pragma unroll
            for (int q = 0; q < 4; q++) {
                int idx = q * 256 + t;
                int row = idx >> 5;
                int c4  = (idx & 31) * 4;
                cpa16(smem_u32(&Bs[nx][row][c4]), Hbt + (size_t)(j0 + row) * CC + c4);
            }
            if (t < 96) {
                int arr = t >> 5, j = t & 31;
                const float* src = (arr == 0 ? g_er : arr == 1 ? g_R : g_S) + rowbase + j0 + j;
                float* dst = (arr == 0 ? er_s[nx] : arr == 1 ? R_s[nx] : S_s[nx]) + j;
                cpa4(smem_u32(dst), src);
            }
            CP_COMMIT();
        }

#pragma unroll
        for (int ks = 0; ks < 4; ks++) {
            const int kb = ks * 8;
            float er0 = er_s[cur][kb + tig],     R0 = R_s[cur][kb + tig],     S0 = S_s[cur][kb + tig];
            float er1 = er_s[cur][kb + tig + 4], R1 = R_s[cur][kb + tig + 4], S1 = S_s[cur][kb + tig + 4];

            uint32_t Af[2][4];
#pragma unroll
            for (int f = 0; f < 2; f++) {
                float w00 = (elr_[f][0] + er0 > 0.f) ? Pr[f][0] * R0 : Qr[f][0] * S0;
                float w10 = (elr_[f][1] + er0 > 0.f) ? Pr[f][1] * R0 : Qr[f][1] * S0;
                float w01 = (elr_[f][0] + er1 > 0.f) ? Pr[f][0] * R1 : Qr[f][0] * S1;
                float w11 = (elr_[f][1] + er1 > 0.f) ? Pr[f][1] * R1 : Qr[f][1] * S1;
                Af[f][0] = cvt_tf32(w00);
                Af[f][1] = cvt_tf32(w10);
                Af[f][2] = cvt_tf32(w01);
                Af[f][3] = cvt_tf32(w11);
                // Z from the ROUNDED weights: numerator/Z bias cancels
                z[f][0] += __uint_as_float(Af[f][0]) + __uint_as_float(Af[f][2]);
                z[f][1] += __uint_as_float(Af[f][1]) + __uint_as_float(Af[f][3]);
            }

#pragma unroll
            for (int nt = 0; nt < 8; nt++) {
                int n = nb + nt * 8 + gid;
                uint32_t bb0 = __float_as_uint(Bs[cur][kb + tig][n]);
                uint32_t bb1 = __float_as_uint(Bs[cur][kb + tig + 4][n]);
                mma8(acc[0][nt], Af[0][0], Af[0][1], Af[0][2], Af[0][3], bb0, bb1);
                mma8(acc[1][nt], Af[1][0], Af[1][1], Af[1][2], Af[1][3], bb0, bb1);
            }
        }
    }

    // Z reduce over tig (lanes differing in bits 0-1)
#pragma unroll
    for (int f = 0; f < 2; f++)
#pragma unroll
        for (int hh = 0; hh < 2; hh++) {
            z[f][hh] += __shfl_xor_sync(0xFFFFFFFFu, z[f][hh], 1);
            z[f][hh] += __shfl_xor_sync(0xFFFFFFFFu, z[f][hh], 2);
        }

    // epilogue: diag correction + identity + elu
#pragma unroll
    for (int f = 0; f < 2; f++) {
#pragma unroll
        for (int hh = 0; hh < 2; hh++) {
            int i  = i0 + Mg * 32 + f * 16 + gid + hh * 8;
            int gi = rowbase + i;
            float eli = elr_[f][hh], Pi = Pr[f][hh], Qi = Qr[f][hh];
            float eri = g_er[gi], Ri = g_R[gi], Si = g_S[gi];
            float tv  = eli + eri;
            float wiif = (tv > 0.f) ? Pi * Ri : Qi * Si;
            float wii  = __uint_as_float(cvt_tf32(wiif));   // match what the MMA used
            float inv  = 1.f / (z[f][hh] - wii);
            const float* hi = Hb + (size_t)i * CC;
            float* op = Out + (size_t)(b * NN + i) * CC + head * 128;
#pragma unroll
            for (int nt = 0; nt < 8; nt++) {
                int col = nb + nt * 8 + tig * 2;
                float2 hv = *(const float2*)(hi + col);
                float v0 = (acc[f][nt][hh * 2 + 0] - wii * hv.x) * inv + hv.x;
                float v1 = (acc[f][nt][hh * 2 + 1] - wii * hv.y) * inv + hv.y;
                float2 o;
                o.x = v0 > 0.f ? v0 : expm1f(v0);
                o.y = v1 > 0.f ? v1 : expm1f(v1);
                *(float2*)(op + col) = o;
            }
        }
    }
}

// ---------------------------------------------------------------------------
extern "C" void kernel_launch(void* const* d_in, const int* in_sizes, int n_in,
                              void* d_out, int out_size)
{
    const float* x   = (const float*)d_in[0];
    const float* W00 = (const float*)d_in[2];
    const float* b00 = (const float*)d_in[3];
    const float* a00 = (const float*)d_in[4];
    const float* W01 = (const float*)d_in[5];
    const float* b01 = (const float*)d_in[6];
    const float* a01 = (const float*)d_in[7];
    const float* W10 = (const float*)d_in[8];
    const float* b10 = (const float*)d_in[9];
    const float* a10 = (const float*)d_in[10];
    const float* W11 = (const float*)d_in[11];
    const float* b11 = (const float*)d_in[12];
    const float* a11 = (const float*)d_in[13];
    float* out = (float*)d_out;

    float *H, *feat;
    cudaGetSymbolAddress((void**)&H,    g_H);
    cudaGetSymbolAddress((void**)&feat, g_feat);

    dim3 gemm_grid(MM / 128, 2);
    dim3 attn_grid(NN / 128, BB, 2);

    // ---- Layer 1 ----
    gemm_mma_kernel<<<gemm_grid, 256>>>(x, W00, W01, b00, b01, H);
    elr_kernel<<<(2 * MM) / 8, 256>>>(a00, a01, H);
    maxpqrs_kernel<<<16, 256>>>();
    attn_mma_kernel<<<attn_grid, 256>>>(H, feat);

    // ---- Layer 2 ----
    gemm_mma_kernel<<<gemm_grid, 256>>>(feat, W10, W11, b10, b11, H);
    elr_kernel<<<(2 * MM) / 8, 256>>>(a10, a11, H);
    maxpqrs_kernel<<<16, 256>>>();
    attn_mma_kernel<<<attn_grid, 256>>>(H, out);
}

// round 7
// speedup vs baseline: 5.3959x; 1.5075x over previous
#include <cuda_runtime.h>
#include <cuda_fp16.h>
#include <math.h>
#include <stdint.h>

#define BB 8
#define NN 2048
#define CC 256
#define MM (BB*NN)   // 16384

// ---------------- scratch ----------------
__device__ float  g_H[MM*CC];       // h (row-major, exact fp32)
__device__ __half g_Hh[MM*CC];      // h fp16 (attention B operand)
__device__ float  g_feat[MM*CC];    // layer-2 input
__device__ float  g_el[2*MM];
__device__ float  g_er[2*MM];
__device__ __half g_elh[2*MM];
__device__ __half g_erh[2*MM];
__device__ __half g_Rh[2*MM];       // exp(er - ermax)
__device__ __half g_Sh[2*MM];       // exp(0.2(er - ermax))
__device__ __half g_Qh[2*MM];       // exp(-0.8*max(el+ermax,0))

// ---------------- helpers ----------------
__device__ __forceinline__ uint32_t smem_u32(const void* p) {
    uint32_t a;
    asm("{ .reg .u64 t; cvta.to.shared.u64 t, %1; cvt.u32.u64 %0, t; }" : "=r"(a) : "l"(p));
    return a;
}
__device__ __forceinline__ uint32_t cvt_tf32(float f) {
    uint32_t r; asm("cvt.rna.tf32.f32 %0, %1;" : "=r"(r) : "f"(f)); return r;
}
__device__ __forceinline__ void cpa16(uint32_t d, const void* s) {
    asm volatile("cp.async.ca.shared.global [%0], [%1], 16;" :: "r"(d), "l"(s));
}
#define CP_COMMIT() asm volatile("cp.async.commit_group;" ::: "memory")
#define CP_WAIT0()  asm volatile("cp.async.wait_group 0;" ::: "memory")

__device__ __forceinline__ void mma8(float* c, uint32_t a0, uint32_t a1,
                                     uint32_t a2, uint32_t a3,
                                     uint32_t b0, uint32_t b1) {
    asm volatile("mma.sync.aligned.m16n8k8.row.col.f32.tf32.tf32.f32 "
        "{%0,%1,%2,%3}, {%4,%5,%6,%7}, {%8,%9}, {%0,%1,%2,%3};"
        : "+f"(c[0]), "+f"(c[1]), "+f"(c[2]), "+f"(c[3])
        : "r"(a0), "r"(a1), "r"(a2), "r"(a3), "r"(b0), "r"(b1));
}
__device__ __forceinline__ void mma16(float* c, const uint32_t* a,
                                      uint32_t b0, uint32_t b1) {
    asm volatile("mma.sync.aligned.m16n8k16.row.col.f32.f16.f16.f32 "
        "{%0,%1,%2,%3}, {%4,%5,%6,%7}, {%8,%9}, {%0,%1,%2,%3};"
        : "+f"(c[0]), "+f"(c[1]), "+f"(c[2]), "+f"(c[3])
        : "r"(a[0]), "r"(a[1]), "r"(a[2]), "r"(a[3]), "r"(b0), "r"(b1));
}
__device__ __forceinline__ void ldsm4t(uint32_t& r0, uint32_t& r1,
                                       uint32_t& r2, uint32_t& r3, uint32_t addr) {
    asm volatile("ldmatrix.sync.aligned.m8n8.x4.trans.shared.b16 {%0,%1,%2,%3}, [%4];"
        : "=r"(r0), "=r"(r1), "=r"(r2), "=r"(r3) : "r"(addr));
}

// fp16x2 weight pair: w = (el+er > 0) ? R : Q*S
__device__ __forceinline__ uint32_t wgt2(uint32_t el2, uint32_t q2, uint32_t er2,
                                         uint32_t r2, uint32_t s2) {
    __half2 t = __hadd2(*(__half2*)&el2, *(__half2*)&er2);
    uint32_t m = __hgt2_mask(t, __half2(__float2half_rn(0.f), __float2half_rn(0.f)));
    __half2 qs = __hmul2(*(__half2*)&q2, *(__half2*)&s2);
    uint32_t qsu = *(uint32_t*)&qs;
    return (r2 & m) | (qsu & ~m);
}

// ---------------------------------------------------------------------------
// K1: h = X @ W + b via 3-term tf32 split (near-fp32 accuracy).
// grid = (M/128, 2), block = 256. Writes exact h to C and fp16 h to g_Hh.
// ---------------------------------------------------------------------------
__global__ __launch_bounds__(256) void gemm_mma_kernel(
    const float* __restrict__ X,
    const float* __restrict__ W0, const float* __restrict__ W1,
    const float* __restrict__ b0_, const float* __restrict__ b1_,
    float* __restrict__ C)
{
    __shared__ float Xs[128][36];
    __shared__ float Ws[32][136];

    const int head = blockIdx.y;
    const float* __restrict__ W    = head ? W1 : W0;
    const float* __restrict__ bias = head ? b1_ : b0_;
    const int m0 = blockIdx.x * 128;

    const int t = threadIdx.x, warp = t >> 5, lane = t & 31;
    const int gid = lane >> 2, tig = lane & 3;
    const int Mg = warp >> 1, Ng = warp & 1;
    const int nb = Ng * 64;

    float acc[2][8][4];
#pragma unroll
    for (int f = 0; f < 2; f++)
#pragma unroll
        for (int nt = 0; nt < 8; nt++)
#pragma unroll
            for (int c = 0; c < 4; c++) acc[f][nt][c] = 0.f;

    for (int k0 = 0; k0 < 256; k0 += 32) {
        __syncthreads();
#pragma unroll
        for (int q = 0; q < 4; q++) {
            int idx = q * 256 + t;
            int row = idx >> 3;
            int c4  = (idx & 7) * 4;
            *(float4*)&Xs[row][c4] =
                *(const float4*)(X + (size_t)(m0 + row) * CC + k0 + c4);
        }
#pragma unroll
        for (int q = 0; q < 4; q++) {
            int idx = q * 256 + t;
            int kk  = idx >> 5;
            int n4  = (idx & 31) * 4;
            *(float4*)&Ws[kk][n4] = *(const float4*)(W + (size_t)(k0 + kk) * 128 + n4);
        }
        __syncthreads();

#pragma unroll
        for (int ks = 0; ks < 4; ks++) {
            const int kb = ks * 8;
            uint32_t Ah[2][4], Al[2][4];
#pragma unroll
            for (int f = 0; f < 2; f++) {
                int r0 = Mg * 32 + f * 16 + gid;
                float v[4];
                v[0] = Xs[r0][kb + tig];
                v[1] = Xs[r0 + 8][kb + tig];
                v[2] = Xs[r0][kb + tig + 4];
                v[3] = Xs[r0 + 8][kb + tig + 4];
#pragma unroll
                for (int q = 0; q < 4; q++) {
                    Ah[f][q] = cvt_tf32(v[q]);
                    Al[f][q] = cvt_tf32(v[q] - __uint_as_float(Ah[f][q]));
                }
            }
#pragma unroll
            for (int nt = 0; nt < 8; nt++) {
                int n = nb + nt * 8 + gid;
                float w0 = Ws[kb + tig][n];
                float w1 = Ws[kb + tig + 4][n];
                uint32_t bh0 = cvt_tf32(w0);
                uint32_t bl0 = cvt_tf32(w0 - __uint_as_float(bh0));
                uint32_t bh1 = cvt_tf32(w1);
                uint32_t bl1 = cvt_tf32(w1 - __uint_as_float(bh1));
#pragma unroll
                for (int f = 0; f < 2; f++) {
                    mma8(acc[f][nt], Ah[f][0], Ah[f][1], Ah[f][2], Ah[f][3], bl0, bl1);
                    mma8(acc[f][nt], Al[f][0], Al[f][1], Al[f][2], Al[f][3], bh0, bh1);
                    mma8(acc[f][nt], Ah[f][0], Ah[f][1], Ah[f][2], Ah[f][3], bh0, bh1);
                }
            }
        }
    }

#pragma unroll
    for (int f = 0; f < 2; f++) {
        int r0 = m0 + Mg * 32 + f * 16 + gid;
#pragma unroll
        for (int nt = 0; nt < 8; nt++) {
            int n = nb + nt * 8 + tig * 2;
            float2 bv = *(const float2*)(bias + n);
            float2 o0, o1;
            o0.x = acc[f][nt][0] + bv.x;
            o0.y = acc[f][nt][1] + bv.y;
            o1.x = acc[f][nt][2] + bv.x;
            o1.y = acc[f][nt][3] + bv.y;
            size_t off0 = (size_t)r0 * 256 + head * 128 + n;
            size_t off1 = (size_t)(r0 + 8) * 256 + head * 128 + n;
            *(float2*)(C + off0) = o0;
            *(float2*)(C + off1) = o1;
            *(__half2*)(g_Hh + off0) = __floats2half2_rn(o0.x, o0.y);
            *(__half2*)(g_Hh + off1) = __floats2half2_rn(o1.x, o1.y);
        }
    }
}

// ---------------------------------------------------------------------------
// K2: el/er per (head,row)
// ---------------------------------------------------------------------------
__global__ __launch_bounds__(256) void elr_kernel(
    const float* __restrict__ a0, const float* __restrict__ a1,
    const float* __restrict__ H)
{
    int gw   = (blockIdx.x * blockDim.x + threadIdx.x) >> 5;
    int lane = threadIdx.x & 31;
    if (gw >= 2 * MM) return;
    int head = gw >> 14;
    int row  = gw & (MM - 1);
    const float* __restrict__ a = head ? a1 : a0;
    const float* __restrict__ h = H + (size_t)row * 256 + head * 128;

    float el = 0.f, er = 0.f;
#pragma unroll
    for (int i = 0; i < 4; i++) {
        int idx = lane + i * 32;
        float hv = h[idx];
        el += hv * a[idx];
        er += hv * a[128 + idx];
    }
#pragma unroll
    for (int o = 16; o > 0; o >>= 1) {
        el += __shfl_xor_sync(0xFFFFFFFFu, el, o);
        er += __shfl_xor_sync(0xFFFFFFFFu, er, o);
    }
    if (lane == 0) { g_el[gw] = el; g_er[gw] = er; }
}

// ---------------------------------------------------------------------------
// K3: per (head,b): ermax, then fp16 R~ = exp(er-ermax), S~ = exp(.2(er-ermax)),
// Q = exp(-0.8*max(el+ermax,0)), plus fp16 el/er for the branch predicate.
// ---------------------------------------------------------------------------
__global__ __launch_bounds__(256) void maxpqrs_kernel()
{
    int head = blockIdx.x >> 3;
    int b    = blockIdx.x & 7;
    int base = head * MM + b * NN;

    __shared__ float red[256];
    float m = -1e30f;
    for (int i = threadIdx.x; i < NN; i += 256) m = fmaxf(m, g_er[base + i]);
    red[threadIdx.x] = m;
    __syncthreads();
    for (int s = 128; s > 0; s >>= 1) {
        if (threadIdx.x < s) red[threadIdx.x] = fmaxf(red[threadIdx.x], red[threadIdx.x + s]);
        __syncthreads();
    }
    float ermax = red[0];

    for (int i = threadIdx.x; i < NN; i += 256) {
        float el = g_el[base + i];
        float er = g_er[base + i];
        float v  = el + ermax;
        g_elh[base + i] = __float2half(el);
        g_erh[base + i] = __float2half(er);
        g_Rh[base + i]  = __float2half(expf(er - ermax));
        g_Sh[base + i]  = __float2half(expf(0.2f * (er - ermax)));
        g_Qh[base + i]  = __float2half(v > 0.f ? expf(-0.8f * v) : 1.0f);
    }
}

// ---------------------------------------------------------------------------
// K4: attention via fp16 mma m16n8k16. CTA = (b, head, 128 i-rows).
// 8 warps = 4 Mg x 2 Ng; warp tile M=32 x N=64. 32-j chunks, cp.async
// double-buffered. Weights built in half2 regs; B via ldmatrix.x4.trans;
// Z via ones-column MMA (exactly consistent with rounded weights).
// grid = (16, 8, 2), block = 256
// ---------------------------------------------------------------------------
#define BROW 136                      // halfs per B smem row (272B, conflict-free LDSM)
#define BUFB (32*BROW*2)              // bytes per B buffer = 8704

__global__ __launch_bounds__(256, 2) void attn_mma_kernel(
    const float* __restrict__ H, float* __restrict__ Out)
{
    __shared__ __half Bs[2][32][BROW];
    __shared__ __half er_s[2][32], R_s[2][32], S_s[2][32];
    __shared__ __half elh_s[128], Qh_s[128];

    const int t = threadIdx.x, warp = t >> 5, lane = t & 31;
    const int gid = lane >> 2, tig = lane & 3;
    const int Mg = warp >> 1, Ng = warp & 1;
    const int nb = Ng * 64;

    const int head = blockIdx.z, b = blockIdx.y, i0 = blockIdx.x * 128;
    const int rowbase = head * MM + b * NN;
    const float*  __restrict__ Hb  = H + (size_t)b * NN * CC + head * 128;
    const __half* __restrict__ Hbh = g_Hh + (size_t)b * NN * CC + head * 128;

    if (t < 128) {
        elh_s[t] = g_elh[rowbase + i0 + t];
        Qh_s[t]  = g_Qh[rowbase + i0 + t];
    }

    // ---- prologue: stage chunk 0 into buffer 0 ----
    {
#pragma unroll
        for (int q = 0; q < 2; q++) {
            int idx = q * 256 + t;
            int row = idx >> 4;
            int seg = idx & 15;
            cpa16(smem_u32(&Bs[0][row][seg * 8]), Hbh + (size_t)row * CC + seg * 8);
        }
        if (t < 12) {
            int arr = t >> 2, q = t & 3;
            const __half* src = (arr == 0 ? g_erh : arr == 1 ? g_Rh : g_Sh) + rowbase + q * 8;
            __half* dst = (arr == 0 ? er_s[0] : arr == 1 ? R_s[0] : S_s[0]) + q * 8;
            cpa16(smem_u32(dst), src);
        }
        CP_COMMIT();
    }
    __syncthreads();

    // per-thread row constants as half2 broadcasts (4 rows: 2 frags x {low,high})
    uint32_t el2[2][2], Q2[2][2];
#pragma unroll
    for (int f = 0; f < 2; f++)
#pragma unroll
        for (int hh = 0; hh < 2; hh++) {
            int r = Mg * 32 + f * 16 + gid + hh * 8;
            uint32_t e = (uint32_t)__half_as_ushort(elh_s[r]);
            uint32_t q = (uint32_t)__half_as_ushort(Qh_s[r]);
            el2[f][hh] = e * 0x00010001u;
            Q2[f][hh]  = q * 0x00010001u;
        }

    float acc[2][8][4];
    float zac[2][4];
#pragma unroll
    for (int f = 0; f < 2; f++) {
#pragma unroll
        for (int c = 0; c < 4; c++) zac[f][c] = 0.f;
#pragma unroll
        for (int nt = 0; nt < 8; nt++)
#pragma unroll
            for (int c = 0; c < 4; c++) acc[f][nt][c] = 0.f;
    }

    // ldmatrix static address part:
    // matrix m = lane>>3 : (m&1) = k-half, (m>>1) = nt sub-block; row r = lane&7
    const int mm_ = lane >> 3, rsub = lane & 7;
    const uint32_t lbase = smem_u32(&Bs[0][0][0])
        + (uint32_t)(((mm_ & 1) * 8 + rsub) * (BROW * 2) + ((mm_ >> 1) * 8 + nb) * 2);

    const uint32_t ONES = 0x3C003C00u;   // half2(1.0, 1.0)

    for (int ch = 0; ch < 64; ch++) {
        const int cur = ch & 1;
        CP_WAIT0();
        __syncthreads();

        if (ch < 63) {
            const int nx = cur ^ 1;
            const int j0 = (ch + 1) * 32;
#pragma unroll
            for (int q = 0; q < 2; q++) {
                int idx = q * 256 + t;
                int row = idx >> 4;
                int seg = idx & 15;
                cpa16(smem_u32(&Bs[nx][row][seg * 8]), Hbh + (size_t)(j0 + row) * CC + seg * 8);
            }
            if (t < 12) {
                int arr = t >> 2, q = t & 3;
                const __half* src = (arr == 0 ? g_erh : arr == 1 ? g_Rh : g_Sh)
                                    + rowbase + j0 + q * 8;
                __half* dst = (arr == 0 ? er_s[nx] : arr == 1 ? R_s[nx] : S_s[nx]) + q * 8;
                cpa16(smem_u32(dst), src);
            }
            CP_COMMIT();
        }

        const uint32_t bbase = lbase + (uint32_t)cur * BUFB;

#pragma unroll
        for (int ks = 0; ks < 2; ks++) {
            const int jl = ks * 16 + tig * 2;
            uint32_t er2l = *(const uint32_t*)&er_s[cur][jl];
            uint32_t er2h = *(const uint32_t*)&er_s[cur][jl + 8];
            uint32_t R2l  = *(const uint32_t*)&R_s[cur][jl];
            uint32_t R2h  = *(const uint32_t*)&R_s[cur][jl + 8];
            uint32_t S2l  = *(const uint32_t*)&S_s[cur][jl];
            uint32_t S2h  = *(const uint32_t*)&S_s[cur][jl + 8];

            uint32_t A[2][4];
#pragma unroll
            for (int f = 0; f < 2; f++) {
                A[f][0] = wgt2(el2[f][0], Q2[f][0], er2l, R2l, S2l);
                A[f][1] = wgt2(el2[f][1], Q2[f][1], er2l, R2l, S2l);
                A[f][2] = wgt2(el2[f][0], Q2[f][0], er2h, R2h, S2h);
                A[f][3] = wgt2(el2[f][1], Q2[f][1], er2h, R2h, S2h);
            }

            // Z row-sums via ones column (consistent with rounded A)
            mma16(zac[0], A[0], ONES, ONES);
            mma16(zac[1], A[1], ONES, ONES);

            const uint32_t kaddr = bbase + (uint32_t)ks * (16 * BROW * 2);
#pragma unroll
            for (int pnt = 0; pnt < 4; pnt++) {
                uint32_t b0a, b1a, b0b, b1b;
                ldsm4t(b0a, b1a, b0b, b1b, kaddr + pnt * 32);
                mma16(acc[0][pnt * 2],     A[0], b0a, b1a);
                mma16(acc[1][pnt * 2],     A[1], b0a, b1a);
                mma16(acc[0][pnt * 2 + 1], A[0], b0b, b1b);
                mma16(acc[1][pnt * 2 + 1], A[1], b0b, b1b);
            }
        }
    }

    // epilogue: diag correction + identity + elu
    const __half h0 = __float2half_rn(0.f);
#pragma unroll
    for (int f = 0; f < 2; f++) {
#pragma unroll
        for (int hh = 0; hh < 2; hh++) {
            int i  = i0 + Mg * 32 + f * 16 + gid + hh * 8;
            int gi = rowbase + i;
            float Z = zac[f][hh * 2];
            // wii mirrored in fp16 exactly as the MMA A path computed it
            __half th = __hadd(g_elh[gi], g_erh[gi]);
            __half wh = __hgt(th, h0) ? g_Rh[gi] : __hmul(g_Qh[gi], g_Sh[gi]);
            float wii = __half2float(wh);
            float inv = 1.f / (Z - wii);
            const float* hi = Hb + (size_t)i * CC;
            float* op = Out + (size_t)(b * NN + i) * CC + head * 128;
#pragma unroll
            for (int nt = 0; nt < 8; nt++) {
                int col = nb + nt * 8 + tig * 2;
                float2 hv = *(const float2*)(hi + col);
                float v0 = (acc[f][nt][hh * 2 + 0] - wii * hv.x) * inv + hv.x;
                float v1 = (acc[f][nt][hh * 2 + 1] - wii * hv.y) * inv + hv.y;
                float2 o;
                o.x = v0 > 0.f ? v0 : expm1f(v0);
                o.y = v1 > 0.f ? v1 : expm1f(v1);
                *(float2*)(op + col) = o;
            }
        }
    }
}

// ---------------------------------------------------------------------------
extern "C" void kernel_launch(void* const* d_in, const int* in_sizes, int n_in,
                              void* d_out, int out_size)
{
    const float* x   = (const float*)d_in[0];
    const float* W00 = (const float*)d_in[2];
    const float* b00 = (const float*)d_in[3];
    const float* a00 = (const float*)d_in[4];
    const float* W01 = (const float*)d_in[5];
    const float* b01 = (const float*)d_in[6];
    const float* a01 = (const float*)d_in[7];
    const float* W10 = (const float*)d_in[8];
    const float* b10 = (const float*)d_in[9];
    const float* a10 = (const float*)d_in[10];
    const float* W11 = (const float*)d_in[11];
    const float* b11 = (const float*)d_in[12];
    const float* a11 = (const float*)d_in[13];
    float* out = (float*)d_out;

    float *H, *feat;
    cudaGetSymbolAddress((void**)&H,    g_H);
    cudaGetSymbolAddress((void**)&feat, g_feat);

    dim3 gemm_grid(MM / 128, 2);
    dim3 attn_grid(NN / 128, BB, 2);

    // ---- Layer 1 ----
    gemm_mma_kernel<<<gemm_grid, 256>>>(x, W00, W01, b00, b01, H);
    elr_kernel<<<(2 * MM) / 8, 256>>>(a00, a01, H);
    maxpqrs_kernel<<<16, 256>>>();
    attn_mma_kernel<<<attn_grid, 256>>>(H, feat);

    // ---- Layer 2 ----
    gemm_mma_kernel<<<gemm_grid, 256>>>(feat, W10, W11, b10, b11, H);
    elr_kernel<<<(2 * MM) / 8, 256>>>(a10, a11, H);
    maxpqrs_kernel<<<16, 256>>>();
    attn_mma_kernel<<<attn_grid, 256>>>(H, out);
}